// round 4
// baseline (speedup 1.0000x reference)
#include <cuda_runtime.h>
#include <cuda_bf16.h>
#include <math_constants.h>

// Problem constants
#define BATCH   8
#define SEQ     4096
#define DIM     256
#define HEADS   8
#define HD      32
#define NFREQ   17          // HD/2 + 1
#define ROWS    (BATCH*SEQ) // 32768
#define BH      (BATCH*HEADS) // 64

// ---------------- scratch (static __device__ — no allocations allowed) ----------------
__device__ float  g_lin[3][(size_t)ROWS * DIM];            // ql, kl, vl
__device__ float2 g_QK[2][(size_t)BH * NFREQ * SEQ];       // Qhat, Khat (seq-major per (b,h,f))
__device__ float2 g_P[(size_t)BH * NFREQ * SEQ];           // product after inverse seq-FFT

// =====================================================================================
// Kernel 1: fused QKV GEMM   out[i,j] = sum_k X[i,k] * W[j,k] + b[j]
// BM=128 BN=128 BK=16, 256 threads, 8x8 microtile
// =====================================================================================
__global__ __launch_bounds__(256) void gemm_qkv(
    const float* __restrict__ q, const float* __restrict__ k, const float* __restrict__ v,
    const float* __restrict__ Wq, const float* __restrict__ bq,
    const float* __restrict__ Wk, const float* __restrict__ bk,
    const float* __restrict__ Wv, const float* __restrict__ bv)
{
    const int z = blockIdx.z;
    const float* X    = (z == 0) ? q  : (z == 1) ? k  : v;
    const float* W    = (z == 0) ? Wq : (z == 1) ? Wk : Wv;
    const float* bias = (z == 0) ? bq : (z == 1) ? bk : bv;
    float* out = g_lin[z];

    __shared__ float As[16][128];   // [k][m]
    __shared__ float Bs[16][128];   // [k][n]

    const int tid  = threadIdx.x;
    const int tx   = tid & 15;      // 0..15 (N dir)
    const int ty   = tid >> 4;      // 0..15 (M dir)
    const int row0 = blockIdx.x * 128;
    const int col0 = blockIdx.y * 128;

    float acc[8][8];
#pragma unroll
    for (int i = 0; i < 8; i++)
#pragma unroll
        for (int j = 0; j < 8; j++) acc[i][j] = 0.0f;

    const int ar  = tid >> 2;          // 0..63
    const int ac  = (tid & 3) << 2;    // 0,4,8,12
    const int bc  = tid >> 1;          // 0..127
    const int bk0 = (tid & 1) << 3;    // 0 or 8

    for (int kk = 0; kk < DIM; kk += 16) {
        // load A tile (128 rows x 16 k)
#pragma unroll
        for (int r2 = 0; r2 < 128; r2 += 64) {
            float4 av = *reinterpret_cast<const float4*>(
                &X[(size_t)(row0 + ar + r2) * DIM + kk + ac]);
            As[ac + 0][ar + r2] = av.x;
            As[ac + 1][ar + r2] = av.y;
            As[ac + 2][ar + r2] = av.z;
            As[ac + 3][ar + r2] = av.w;
        }
        // load B tile (128 cols x 16 k): Bs[k'][col] = W[(col0+col)*DIM + kk + k']
        {
            const float* wrow = &W[(size_t)(col0 + bc) * DIM + kk + bk0];
            float4 b0 = *reinterpret_cast<const float4*>(wrow);
            float4 b1 = *reinterpret_cast<const float4*>(wrow + 4);
            Bs[bk0 + 0][bc] = b0.x; Bs[bk0 + 1][bc] = b0.y;
            Bs[bk0 + 2][bc] = b0.z; Bs[bk0 + 3][bc] = b0.w;
            Bs[bk0 + 4][bc] = b1.x; Bs[bk0 + 5][bc] = b1.y;
            Bs[bk0 + 6][bc] = b1.z; Bs[bk0 + 7][bc] = b1.w;
        }
        __syncthreads();
#pragma unroll
        for (int kq = 0; kq < 16; kq++) {
            float4 a0 = *reinterpret_cast<const float4*>(&As[kq][ty * 8]);
            float4 a1 = *reinterpret_cast<const float4*>(&As[kq][ty * 8 + 4]);
            float4 b0 = *reinterpret_cast<const float4*>(&Bs[kq][tx * 8]);
            float4 b1 = *reinterpret_cast<const float4*>(&Bs[kq][tx * 8 + 4]);
            float av[8] = {a0.x, a0.y, a0.z, a0.w, a1.x, a1.y, a1.z, a1.w};
            float bv2[8] = {b0.x, b0.y, b0.z, b0.w, b1.x, b1.y, b1.z, b1.w};
#pragma unroll
            for (int i = 0; i < 8; i++)
#pragma unroll
                for (int j = 0; j < 8; j++)
                    acc[i][j] = fmaf(av[i], bv2[j], acc[i][j]);
        }
        __syncthreads();
    }

    float br[8];
#pragma unroll
    for (int j = 0; j < 8; j++) br[j] = bias[col0 + tx * 8 + j];

#pragma unroll
    for (int i = 0; i < 8; i++) {
        int r = row0 + ty * 8 + i;
        float* orow = &out[(size_t)r * DIM + col0 + tx * 8];
        float4 o0 = make_float4(acc[i][0] + br[0], acc[i][1] + br[1],
                                acc[i][2] + br[2], acc[i][3] + br[3]);
        float4 o1 = make_float4(acc[i][4] + br[4], acc[i][5] + br[5],
                                acc[i][6] + br[6], acc[i][7] + br[7]);
        *reinterpret_cast<float4*>(orow)     = o0;
        *reinterpret_cast<float4*>(orow + 4) = o1;
    }
}

// =====================================================================================
// Kernel 2: rfft over head_dim (32 -> 17 complex bins) for ql and kl.
// 32 tokens per CTA, thread = (token, head). Output layout [bh][f][n] (seq-contiguous).
// =====================================================================================
__global__ __launch_bounds__(256) void rfft_heads()
{
    const int which = blockIdx.y;            // 0 -> Q, 1 -> K
    const float* __restrict__ src = g_lin[which];
    float2* __restrict__ dst = g_QK[which];

    __shared__ float xs[32 * 264];           // padded rows: head h at h*33
    __shared__ float twc[32], tws[32];       // cos/sin(2*pi*k/32)

    const int tid = threadIdx.x;
    if (tid < 32) {
        float s, c;
        sincospif((float)tid * (1.0f / 16.0f), &s, &c);
        twc[tid] = c; tws[tid] = s;
    }
    const int row0 = blockIdx.x * 32;
    for (int i = tid; i < 32 * 256; i += 256) {
        int tok = i >> 8, cc = i & 255;
        xs[tok * 264 + (cc >> 5) * 33 + (cc & 31)] = src[(size_t)row0 * DIM + i];
    }
    __syncthreads();

    const int tok = tid >> 3, h = tid & 7;
    float xr[32];
#pragma unroll
    for (int d = 0; d < 32; d++) xr[d] = xs[tok * 264 + h * 33 + d];

    const int b  = row0 >> 12;
    const int n  = (row0 & (SEQ - 1)) + tok;
    const int bh = b * HEADS + h;

    for (int f = 0; f < NFREQ; f++) {
        float re = 0.0f, im = 0.0f;
#pragma unroll
        for (int d = 0; d < 32; d++) {
            int k2 = (f * d) & 31;
            re = fmaf(xr[d], twc[k2], re);
            im = fmaf(xr[d], -tws[k2], im);
        }
        dst[((size_t)bh * NFREQ + f) * SEQ + n] = make_float2(re, im);
    }
}

// =====================================================================================
// Kernel 3: per (b,h,f) column: FFT4096(Q), FFT4096(K), pointwise mult (scaled),
// inverse FFT4096 -> g_P.  Stockham radix-2 in SMEM (no bit reversal).
// =====================================================================================
__device__ __forceinline__ void fftcore(float2* x, float2* y, const float2* tw,
                                        int tid, bool inv)
{
    float2* a = x; float2* b = y;
#pragma unroll 1
    for (int ls = 0; ls < 12; ls++) {
        const int s = 1 << ls;
#pragma unroll
        for (int t = tid; t < 2048; t += 256) {
            int p = t >> ls;
            int qq = t & (s - 1);
            float2 w = tw[p << ls];
            float wy = inv ? -w.y : w.y;
            float2 u = a[t];
            float2 v = a[t + 2048];
            float2 sum = make_float2(u.x + v.x, u.y + v.y);
            float2 dif = make_float2(u.x - v.x, u.y - v.y);
            int o = qq + (p << (ls + 1));
            b[o]     = sum;
            b[o + s] = make_float2(dif.x * w.x - dif.y * wy,
                                   dif.x * wy  + dif.y * w.x);
        }
        __syncthreads();
        float2* tmp = a; a = b; b = tmp;
    }
    // 12 stages (even) -> result back in x
}

__global__ __launch_bounds__(256) void fft_conv()
{
    extern __shared__ unsigned char smraw[];
    float2* tw = reinterpret_cast<float2*>(smraw);   // 2048
    float2* bq = tw + 2048;                          // 4096 (Qhat)
    float2* ba = bq + 4096;                          // 4096 work A
    float2* bb = ba + 4096;                          // 4096 work B

    const int tid = threadIdx.x;
    const int f   = blockIdx.x;      // 0..16
    const int bh  = blockIdx.y;      // 0..63
    const size_t base = ((size_t)bh * NFREQ + f) * SEQ;

    for (int i = tid; i < 2048; i += 256) {
        float s, c;
        sincospif((float)i * (1.0f / 2048.0f), &s, &c);
        tw[i] = make_float2(c, -s);
    }
    for (int i = tid; i < 4096; i += 256) ba[i] = g_QK[0][base + i];
    __syncthreads();

    fftcore(ba, bb, tw, tid, false);                 // Qhat in ba
    for (int i = tid; i < 4096; i += 256) bq[i] = ba[i];
    __syncthreads();

    for (int i = tid; i < 4096; i += 256) ba[i] = g_QK[1][base + i];
    __syncthreads();
    fftcore(ba, bb, tw, tid, false);                 // Khat in ba

    const float scale = 1.0f / 131072.0f;            // 1/(4096*32): both inverse norms
    for (int i = tid; i < 4096; i += 256) {
        float2 a = ba[i], q2 = bq[i];
        ba[i] = make_float2((a.x * q2.x - a.y * q2.y) * scale,
                            (a.x * q2.y + a.y * q2.x) * scale);
    }
    __syncthreads();
    fftcore(ba, bb, tw, tid, true);                  // inverse -> ba

    for (int i = tid; i < 4096; i += 256) g_P[base + i] = ba[i];
}

// =====================================================================================
// Kernel 4: irfft-32 over heads + softmax(32) + value gate + residual + LayerNorm(256)
// 32 tokens per CTA; warp handles 4 tokens; lane = head_dim index d.
// =====================================================================================
__global__ __launch_bounds__(256) void epilogue(
    const float* __restrict__ vin, const float* __restrict__ gamma,
    const float* __restrict__ beta, float* __restrict__ out)
{
    __shared__ float2 Psm[HEADS * NFREQ * 32];   // [h][f][tok]
    __shared__ float c32[32], s32[32];

    const int tid = threadIdx.x;
    if (tid < 32) {
        float s, c;
        sincospif((float)tid * (1.0f / 16.0f), &s, &c);
        c32[tid] = c; s32[tid] = s;
    }
    const int row0 = blockIdx.x * 32;
    const int b = row0 >> 12, n0 = row0 & (SEQ - 1);

    for (int i = tid; i < HEADS * NFREQ * 32; i += 256) {
        int h = i / (NFREQ * 32);
        int r = i - h * (NFREQ * 32);
        int f = r >> 5, tok = r & 31;
        Psm[i] = g_P[(((size_t)(b * HEADS + h)) * NFREQ + f) * SEQ + n0 + tok];
    }
    __syncthreads();

    const int w = tid >> 5, d = tid & 31;
    const float* __restrict__ vl = g_lin[2];

    for (int it = 0; it < 4; it++) {
        const int tok = w + it * 8;
        const int row = row0 + tok;
        float gh[8];
        float s1 = 0.0f, s2 = 0.0f;
#pragma unroll
        for (int h = 0; h < 8; h++) {
            const float2* Ph = &Psm[h * NFREQ * 32 + tok];
            float acc = Ph[0].x;                       // f = 0 (real)
            float2 F16 = Ph[16 * 32];
            acc += (d & 1) ? -F16.x : F16.x;           // Nyquist (real)
#pragma unroll
            for (int f = 1; f <= 15; f++) {
                float2 F = Ph[f * 32];
                int k2 = (f * d) & 31;
                acc += 2.0f * (F.x * c32[k2] - F.y * s32[k2]);
            }
            // softmax over 32 lanes
            float m = acc;
#pragma unroll
            for (int o = 16; o; o >>= 1) m = fmaxf(m, __shfl_xor_sync(0xffffffffu, m, o));
            float e = __expf(acc - m);
            float ss = e;
#pragma unroll
            for (int o = 16; o; o >>= 1) ss += __shfl_xor_sync(0xffffffffu, ss, o);
            float p = e / ss;
            int c = h * 32 + d;
            float vv = vl[(size_t)row * DIM + c];
            float rv = vin[(size_t)row * DIM + c];
            float g = fmaf(vv, p, rv);                 // gate + residual
            gh[h] = g; s1 += g; s2 = fmaf(g, g, s2);
        }
#pragma unroll
        for (int o = 16; o; o >>= 1) {
            s1 += __shfl_xor_sync(0xffffffffu, s1, o);
            s2 += __shfl_xor_sync(0xffffffffu, s2, o);
        }
        float mean = s1 * (1.0f / 256.0f);
        float var  = s2 * (1.0f / 256.0f) - mean * mean;
        float inv  = rsqrtf(var + 1e-5f);
#pragma unroll
        for (int h = 0; h < 8; h++) {
            int c = h * 32 + d;
            out[(size_t)row * DIM + c] = (gh[h] - mean) * inv * gamma[c] + beta[c];
        }
    }
}

// =====================================================================================
extern "C" void kernel_launch(void* const* d_in, const int* in_sizes, int n_in,
                              void* d_out, int out_size)
{
    const float* q     = (const float*)d_in[0];
    const float* k     = (const float*)d_in[1];
    const float* v     = (const float*)d_in[2];
    const float* Wq    = (const float*)d_in[3];
    const float* bq    = (const float*)d_in[4];
    const float* Wk    = (const float*)d_in[5];
    const float* bk    = (const float*)d_in[6];
    const float* Wv    = (const float*)d_in[7];
    const float* bv    = (const float*)d_in[8];
    const float* gamma = (const float*)d_in[9];
    const float* beta  = (const float*)d_in[10];
    float* out = (float*)d_out;

    const int fft_smem = (2048 + 3 * 4096) * (int)sizeof(float2);  // 114688 B
    cudaFuncSetAttribute(fft_conv, cudaFuncAttributeMaxDynamicSharedMemorySize, fft_smem);

    gemm_qkv<<<dim3(ROWS / 128, DIM / 128, 3), 256>>>(q, k, v, Wq, bq, Wk, bk, Wv, bv);
    rfft_heads<<<dim3(ROWS / 32, 2), 256>>>();
    fft_conv<<<dim3(NFREQ, BH), 256, fft_smem>>>();
    epilogue<<<ROWS / 32, 256>>>(v, gamma, beta, out);
}